// round 1
// baseline (speedup 1.0000x reference)
#include <cuda_runtime.h>
#include <math.h>

#define BB 32
#define TXX 384
#define TYY 1536
#define DIMK 256
#define NF 80
#define NEGF (-1000000000.0f)
#define CONSTF (-73.51508265637381f)   /* -0.5*log(2*pi)*80 */

#define ATTN_SZ ((size_t)BB * TXX * TYY)

// ---------------- scratch (static device memory; no allocation) -------------
__device__ float g_xp[(size_t)BB * NF * TXX];          // [b][f][t]
__device__ float g_xsq[BB * TXX];
__device__ float g_ysq[BB * TYY];
__device__ float g_v[(size_t)BB * TYY * TXX];          // [b][y][t]
__device__ int   g_idx[BB * TYY];
__device__ float g_dur[BB * TXX];

// ---------------------------------------------------------------------------
// y_square[b][s] = -0.5 * sum_f y[b][f][s]^2
__global__ void ysq_kernel(const float* __restrict__ y) {
    int b = blockIdx.y;
    int s = blockIdx.x * 256 + threadIdx.x;
    if (s >= TYY) return;
    const float* yb = y + (size_t)b * NF * TYY + s;
    float sum = 0.f;
#pragma unroll
    for (int f = 0; f < NF; ++f) {
        float v = yb[(size_t)f * TYY];
        sum += v * v;
    }
    g_ysq[b * TYY + s] = -0.5f * sum;
}

// ---------------------------------------------------------------------------
// xp[b][f][t] = sum_d x[b][t][d] * W[f][d] + bias[f];  xsq[b][t] = -0.5*sum_f xp^2
// Block: one batch b, 128 t.  160 threads = 16 t-groups x 10 f-groups, 8x8 tile.
__global__ __launch_bounds__(160) void xp_kernel(const float* __restrict__ x,
                                                 const float* __restrict__ W,
                                                 const float* __restrict__ bias) {
    __shared__ float xs[32][128];   // [k][t]
    __shared__ float ws[32][80];    // [k][f]
    __shared__ float part[10][128];

    int b  = blockIdx.y;
    int t0 = blockIdx.x * 128;
    int tid = threadIdx.x;
    int tx = tid & 15;        // t-group
    int fg = tid >> 4;        // f-group (0..9)

    float acc[8][8];
#pragma unroll
    for (int i = 0; i < 8; ++i)
#pragma unroll
        for (int j = 0; j < 8; ++j) acc[i][j] = 0.f;

    const float* xb = x + ((size_t)b * TXX + t0) * DIMK;

    for (int k0 = 0; k0 < DIMK; k0 += 32) {
        for (int i = tid; i < 1024; i += 160) {     // 128 t x 8 float4
            int t = i >> 3, kq = i & 7;
            float4 v = *(const float4*)(xb + (size_t)t * DIMK + k0 + kq * 4);
            xs[kq * 4 + 0][t] = v.x; xs[kq * 4 + 1][t] = v.y;
            xs[kq * 4 + 2][t] = v.z; xs[kq * 4 + 3][t] = v.w;
        }
        for (int i = tid; i < 640; i += 160) {      // 80 f x 8 float4
            int f = i >> 3, kq = i & 7;
            float4 v = *(const float4*)(W + (size_t)f * DIMK + k0 + kq * 4);
            ws[kq * 4 + 0][f] = v.x; ws[kq * 4 + 1][f] = v.y;
            ws[kq * 4 + 2][f] = v.z; ws[kq * 4 + 3][f] = v.w;
        }
        __syncthreads();
#pragma unroll 8
        for (int kk = 0; kk < 32; ++kk) {
            float4 xa = *(const float4*)&xs[kk][tx * 8];
            float4 xb4 = *(const float4*)&xs[kk][tx * 8 + 4];
            float4 wa = *(const float4*)&ws[kk][fg * 8];
            float4 wb4 = *(const float4*)&ws[kk][fg * 8 + 4];
            float xv[8] = {xa.x, xa.y, xa.z, xa.w, xb4.x, xb4.y, xb4.z, xb4.w};
            float wv[8] = {wa.x, wa.y, wa.z, wa.w, wb4.x, wb4.y, wb4.z, wb4.w};
#pragma unroll
            for (int i = 0; i < 8; ++i)
#pragma unroll
                for (int j = 0; j < 8; ++j) acc[i][j] += xv[i] * wv[j];
        }
        __syncthreads();
    }

    float bv[8];
#pragma unroll
    for (int j = 0; j < 8; ++j) bv[j] = bias[fg * 8 + j];

    float ss[8];
#pragma unroll
    for (int i = 0; i < 8; ++i) ss[i] = 0.f;

#pragma unroll
    for (int i = 0; i < 8; ++i) {
        int t = t0 + tx * 8 + i;
#pragma unroll
        for (int j = 0; j < 8; ++j) {
            float v = acc[i][j] + bv[j];
            g_xp[((size_t)b * NF + fg * 8 + j) * TXX + t] = v;
            ss[i] += v * v;
        }
    }
#pragma unroll
    for (int i = 0; i < 8; ++i) part[fg][tx * 8 + i] = ss[i];
    __syncthreads();
    if (tid < 128) {
        float s = 0.f;
#pragma unroll
        for (int g = 0; g < 10; ++g) s += part[g][tid];
        g_xsq[b * TXX + t0 + tid] = -0.5f * s;
    }
}

// ---------------------------------------------------------------------------
// v[b][y][t] = ysq[y] + sum_f xp[b][f][t]*y[b][f][y] + xsq[t] + CONST  (masked)
// Tile 128y x 128t, 256 threads, 8x8 register tile, K=80.
__global__ __launch_bounds__(256) void cross_kernel(const float* __restrict__ y,
                                                    const int* __restrict__ xl,
                                                    const int* __restrict__ yl) {
    extern __shared__ float sm[];
    float* Ys = sm;            // [80][128]
    float* Xs = sm + 80 * 128; // [80][128]

    int b  = blockIdx.z;
    int y0 = blockIdx.y * 128;
    int t0 = blockIdx.x * 128;
    int ylen = yl[b], xlen = xl[b];
    if (y0 >= ylen) return;

    int tid = threadIdx.x;

    const float* yb = y + (size_t)b * NF * TYY;
    for (int i = tid; i < 2560; i += 256) {
        int f = i >> 5, q = i & 31;
        *(float4*)&Ys[f * 128 + q * 4] =
            *(const float4*)(yb + (size_t)f * TYY + y0 + q * 4);
    }
    const float* xpb = g_xp + (size_t)b * NF * TXX;
    for (int i = tid; i < 2560; i += 256) {
        int f = i >> 5, q = i & 31;
        *(float4*)&Xs[f * 128 + q * 4] =
            *(const float4*)(xpb + (size_t)f * TXX + t0 + q * 4);
    }
    __syncthreads();

    int tx = tid & 15;   // t
    int ty = tid >> 4;   // y

    float acc[8][8];
#pragma unroll
    for (int i = 0; i < 8; ++i)
#pragma unroll
        for (int j = 0; j < 8; ++j) acc[i][j] = 0.f;

#pragma unroll 4
    for (int f = 0; f < NF; ++f) {
        float4 ya = *(const float4*)&Ys[f * 128 + ty * 8];
        float4 yb4 = *(const float4*)&Ys[f * 128 + ty * 8 + 4];
        float4 xa = *(const float4*)&Xs[f * 128 + tx * 8];
        float4 xb4 = *(const float4*)&Xs[f * 128 + tx * 8 + 4];
        float yv[8] = {ya.x, ya.y, ya.z, ya.w, yb4.x, yb4.y, yb4.z, yb4.w};
        float xv[8] = {xa.x, xa.y, xa.z, xa.w, xb4.x, xb4.y, xb4.z, xb4.w};
#pragma unroll
        for (int i = 0; i < 8; ++i)
#pragma unroll
            for (int j = 0; j < 8; ++j) acc[i][j] += yv[i] * xv[j];
    }

    int tbase = t0 + tx * 8;
    float xsqv[8];
#pragma unroll
    for (int j = 0; j < 8; ++j) xsqv[j] = g_xsq[b * TXX + tbase + j];

#pragma unroll
    for (int i = 0; i < 8; ++i) {
        int yg = y0 + ty * 8 + i;
        if (yg >= ylen) continue;
        float ysv = g_ysq[b * TYY + yg];
        float ov[8];
#pragma unroll
        for (int j = 0; j < 8; ++j) {
            float val = ((ysv + acc[i][j]) + xsqv[j]) + CONSTF;
            ov[j] = (tbase + j < xlen) ? val : NEGF;
        }
        float* vout = g_v + ((size_t)b * TYY + yg) * TXX + tbase;
        *(float4*)(vout + 0) = make_float4(ov[0], ov[1], ov[2], ov[3]);
        *(float4*)(vout + 4) = make_float4(ov[4], ov[5], ov[6], ov[7]);
    }
}

// ---------------------------------------------------------------------------
// DP forward + backtrack.  One warp per batch.  Lane L owns t = 12L + j.
// Decision bit (y,t): Q[y-1][t] < Q[y-1][t-1], packed uint16 per lane in smem.
__global__ __launch_bounds__(32) void dp_kernel(const int* __restrict__ xl,
                                                const int* __restrict__ yl) {
    extern __shared__ unsigned short sdec[];   // [TYY][32]
    int b = blockIdx.x;
    int lane = threadIdx.x;
    int ylen = yl[b], xlen = xl[b];

    float q[12];
#pragma unroll
    for (int j = 0; j < 12; ++j) q[j] = NEGF;
    if (lane == 0) q[0] = 0.0f;

    const float* vb = g_v + (size_t)b * TYY * TXX;
    const float4* row = (const float4*)vb + lane * 3;
    float4 c0 = row[0], c1 = row[1], c2 = row[2];
    float4 n0 = c0, n1 = c1, n2 = c2;

    for (int yy = 0; yy < ylen; ++yy) {
        if (yy + 1 < ylen) {
            const float4* nr = (const float4*)(vb + (size_t)(yy + 1) * TXX) + lane * 3;
            n0 = nr[0]; n1 = nr[1]; n2 = nr[2];
        }
        float carry = __shfl_up_sync(0xffffffffu, q[11], 1);
        if (lane == 0) carry = NEGF;
        float vv[12] = {c0.x, c0.y, c0.z, c0.w,
                        c1.x, c1.y, c1.z, c1.w,
                        c2.x, c2.y, c2.z, c2.w};
        unsigned bits = 0u;
#pragma unroll
        for (int j = 11; j >= 1; --j) {
            unsigned lt = (q[j] < q[j - 1]) ? 1u : 0u;
            bits |= lt << j;
            q[j] = vv[j] + fmaxf(q[j], q[j - 1]);
        }
        {
            unsigned lt = (q[0] < carry) ? 1u : 0u;
            bits |= lt;
            q[0] = vv[0] + fmaxf(q[0], carry);
        }
        sdec[yy * 32 + lane] = (unsigned short)bits;
        c0 = n0; c1 = n1; c2 = n2;
    }
    __syncwarp();

#pragma unroll
    for (int j = 0; j < 12; ++j) g_dur[b * TXX + lane * 12 + j] = 0.0f;
    __syncwarp();

    if (lane == 0) {
        int idx = xlen - 1;
        int w = idx / 12, r = idx - w * 12;
        int cnt = 0;
        int* gi = g_idx + b * TYY;
        for (int yy = ylen - 1; yy >= 0; --yy) {
            gi[yy] = idx;
            cnt++;
            bool move = false;
            if (idx != 0 && yy > 0) {
                if (idx == yy) move = true;
                else move = ((sdec[yy * 32 + w] >> r) & 1u) != 0u;
            }
            if (move) {
                g_dur[b * TXX + idx] = (float)cnt;
                cnt = 0;
                idx--;
                if (--r < 0) { r = 11; w--; }
            }
        }
        g_dur[b * TXX + idx] = (float)cnt;
    }
}

// ---------------------------------------------------------------------------
// attn[b][t][s] = (s < ylen && g_idx[b][s] == t) ? 1 : 0
__global__ __launch_bounds__(128) void attn_kernel(const int* __restrict__ yl,
                                                   float* __restrict__ out) {
    int b = blockIdx.y;
    int t = blockIdx.x;
    int tid = threadIdx.x;
    int ylen = yl[b];
    const int* gi = g_idx + b * TYY;
    float* o = out + ((size_t)b * TXX + t) * TYY;
#pragma unroll
    for (int it = 0; it < 3; ++it) {
        int s4 = tid + it * 128;
        int s = s4 * 4;
        int4 iv = *(const int4*)(gi + s);
        float4 ov;
        ov.x = (s + 0 < ylen && iv.x == t) ? 1.f : 0.f;
        ov.y = (s + 1 < ylen && iv.y == t) ? 1.f : 0.f;
        ov.z = (s + 2 < ylen && iv.z == t) ? 1.f : 0.f;
        ov.w = (s + 3 < ylen && iv.w == t) ? 1.f : 0.f;
        *(float4*)(o + s) = ov;
    }
}

// ---------------------------------------------------------------------------
// loss + durations tail
__global__ __launch_bounds__(256) void loss_kernel(const float* __restrict__ pred,
                                                   const int* __restrict__ xl,
                                                   float* __restrict__ out,
                                                   int write_tail) {
    __shared__ float red[256];
    int tid = threadIdx.x;
    float s = 0.f;
    for (int i = tid; i < BB * TXX; i += 256) {
        int b = i / TXX, t = i - b * TXX;
        float dur = g_dur[i];
        float tl = (t < xl[b]) ? logf(dur + 1e-8f) : 0.0f;
        float d = pred[i] - tl;
        s += d * d;
        if (write_tail) out[ATTN_SZ + 1 + i] = dur;
    }
    red[tid] = s;
    __syncthreads();
    for (int off = 128; off > 0; off >>= 1) {
        if (tid < off) red[tid] += red[tid + off];
        __syncthreads();
    }
    if (tid == 0 && write_tail) {
        int sx = 0;
        for (int bb2 = 0; bb2 < BB; ++bb2) sx += xl[bb2];
        out[ATTN_SZ] = red[0] / (float)sx;
    }
}

// ---------------------------------------------------------------------------
extern "C" void kernel_launch(void* const* d_in, const int* in_sizes, int n_in,
                              void* d_out, int out_size) {
    const float* x    = (const float*)d_in[0];
    const float* y    = (const float*)d_in[1];
    // d_in[2] = x_mask, d_in[3] = y_mask (implied by lengths; unused)
    const int*   xlen = (const int*)d_in[4];
    const int*   ylen = (const int*)d_in[5];
    const float* pred = (const float*)d_in[6];
    const float* W    = (const float*)d_in[7];
    const float* bias = (const float*)d_in[8];
    float* out = (float*)d_out;

    cudaFuncSetAttribute(cross_kernel, cudaFuncAttributeMaxDynamicSharedMemorySize,
                         2 * 80 * 128 * (int)sizeof(float));
    cudaFuncSetAttribute(dp_kernel, cudaFuncAttributeMaxDynamicSharedMemorySize,
                         TYY * 32 * (int)sizeof(unsigned short));

    ysq_kernel<<<dim3(TYY / 256, BB), 256>>>(y);
    xp_kernel<<<dim3(TXX / 128, BB), 160>>>(x, W, bias);
    cross_kernel<<<dim3(TXX / 128, TYY / 128, BB), 256,
                   2 * 80 * 128 * sizeof(float)>>>(y, xlen, ylen);
    dp_kernel<<<BB, 32, TYY * 32 * sizeof(unsigned short)>>>(xlen, ylen);
    attn_kernel<<<dim3(TXX, BB), 128>>>(ylen, out);

    int write_tail = ((size_t)out_size >= ATTN_SZ + 1 + BB * TXX) ? 1 : 0;
    loss_kernel<<<1, 256>>>(pred, xlen, out, write_tail);
}

// round 3
// speedup vs baseline: 1.8557x; 1.8557x over previous
#include <cuda_runtime.h>
#include <stdint.h>
#include <math.h>

#define BB 32
#define TXX 384
#define TYY 1536
#define DIMK 256
#define NF 80
#define NEGF (-1000000000.0f)
#define CONSTF (-73.51508265637381f)   /* -0.5*log(2*pi)*80 */

#define ATTN_SZ ((size_t)BB * TXX * TYY)

// DP pipeline depth
#define DSLOT 16
#define PF 14

// ---------------- scratch (static device memory; no allocation) -------------
__device__ float g_xp[(size_t)BB * NF * TXX];          // [b][f][t]
__device__ float g_xsq[BB * TXX];
__device__ float g_ysq[BB * TYY];
__device__ float g_v[(size_t)BB * TYY * TXX];          // [b][y][t]
__device__ int   g_idx[BB * TYY];
__device__ float g_dur[BB * TXX];

// ---------------------------------------------------------------------------
__device__ __forceinline__ void cp16(uint32_t s, const void* g) {
    asm volatile("cp.async.cg.shared.global [%0], [%1], 16;\n" :: "r"(s), "l"(g));
}

// ---------------------------------------------------------------------------
// y_square[b][s] = -0.5 * sum_f y[b][f][s]^2
__global__ void ysq_kernel(const float* __restrict__ y) {
    int b = blockIdx.y;
    int s = blockIdx.x * 256 + threadIdx.x;
    if (s >= TYY) return;
    const float* yb = y + (size_t)b * NF * TYY + s;
    float sum = 0.f;
#pragma unroll
    for (int f = 0; f < NF; ++f) {
        float v = yb[(size_t)f * TYY];
        sum += v * v;
    }
    g_ysq[b * TYY + s] = -0.5f * sum;
}

// ---------------------------------------------------------------------------
// xp[b][f][t] = sum_d x[b][t][d] * W[f][d] + bias[f];  xsq[b][t] = -0.5*sum_f xp^2
__global__ __launch_bounds__(160) void xp_kernel(const float* __restrict__ x,
                                                 const float* __restrict__ W,
                                                 const float* __restrict__ bias) {
    __shared__ float xs[32][128];   // [k][t]
    __shared__ float ws[32][80];    // [k][f]
    __shared__ float part[10][128];

    int b  = blockIdx.y;
    int t0 = blockIdx.x * 128;
    int tid = threadIdx.x;
    int tx = tid & 15;        // t-group
    int fg = tid >> 4;        // f-group (0..9)

    float acc[8][8];
#pragma unroll
    for (int i = 0; i < 8; ++i)
#pragma unroll
        for (int j = 0; j < 8; ++j) acc[i][j] = 0.f;

    const float* xb = x + ((size_t)b * TXX + t0) * DIMK;

    for (int k0 = 0; k0 < DIMK; k0 += 32) {
        for (int i = tid; i < 1024; i += 160) {     // 128 t x 8 float4
            int t = i >> 3, kq = i & 7;
            float4 v = *(const float4*)(xb + (size_t)t * DIMK + k0 + kq * 4);
            xs[kq * 4 + 0][t] = v.x; xs[kq * 4 + 1][t] = v.y;
            xs[kq * 4 + 2][t] = v.z; xs[kq * 4 + 3][t] = v.w;
        }
        for (int i = tid; i < 640; i += 160) {      // 80 f x 8 float4
            int f = i >> 3, kq = i & 7;
            float4 v = *(const float4*)(W + (size_t)f * DIMK + k0 + kq * 4);
            ws[kq * 4 + 0][f] = v.x; ws[kq * 4 + 1][f] = v.y;
            ws[kq * 4 + 2][f] = v.z; ws[kq * 4 + 3][f] = v.w;
        }
        __syncthreads();
#pragma unroll 8
        for (int kk = 0; kk < 32; ++kk) {
            float4 xa = *(const float4*)&xs[kk][tx * 8];
            float4 xb4 = *(const float4*)&xs[kk][tx * 8 + 4];
            float4 wa = *(const float4*)&ws[kk][fg * 8];
            float4 wb4 = *(const float4*)&ws[kk][fg * 8 + 4];
            float xv[8] = {xa.x, xa.y, xa.z, xa.w, xb4.x, xb4.y, xb4.z, xb4.w};
            float wv[8] = {wa.x, wa.y, wa.z, wa.w, wb4.x, wb4.y, wb4.z, wb4.w};
#pragma unroll
            for (int i = 0; i < 8; ++i)
#pragma unroll
                for (int j = 0; j < 8; ++j) acc[i][j] += xv[i] * wv[j];
        }
        __syncthreads();
    }

    float bv[8];
#pragma unroll
    for (int j = 0; j < 8; ++j) bv[j] = bias[fg * 8 + j];

    float ss[8];
#pragma unroll
    for (int i = 0; i < 8; ++i) ss[i] = 0.f;

#pragma unroll
    for (int i = 0; i < 8; ++i) {
        int t = t0 + tx * 8 + i;
#pragma unroll
        for (int j = 0; j < 8; ++j) {
            float v = acc[i][j] + bv[j];
            g_xp[((size_t)b * NF + fg * 8 + j) * TXX + t] = v;
            ss[i] += v * v;
        }
    }
#pragma unroll
    for (int i = 0; i < 8; ++i) part[fg][tx * 8 + i] = ss[i];
    __syncthreads();
    if (tid < 128) {
        float s = 0.f;
#pragma unroll
        for (int g = 0; g < 10; ++g) s += part[g][tid];
        g_xsq[b * TXX + t0 + tid] = -0.5f * s;
    }
}

// ---------------------------------------------------------------------------
// v[b][y][t] = ysq[y] + sum_f xp[b][f][t]*y[b][f][y] + xsq[t] + CONST  (masked)
__global__ __launch_bounds__(256) void cross_kernel(const float* __restrict__ y,
                                                    const int* __restrict__ xl,
                                                    const int* __restrict__ yl) {
    extern __shared__ float sm[];
    float* Ys = sm;            // [80][128]
    float* Xs = sm + 80 * 128; // [80][128]

    int b  = blockIdx.z;
    int y0 = blockIdx.y * 128;
    int t0 = blockIdx.x * 128;
    int ylen = yl[b], xlen = xl[b];
    if (y0 >= ylen) return;

    int tid = threadIdx.x;

    const float* yb = y + (size_t)b * NF * TYY;
    for (int i = tid; i < 2560; i += 256) {
        int f = i >> 5, q = i & 31;
        *(float4*)&Ys[f * 128 + q * 4] =
            *(const float4*)(yb + (size_t)f * TYY + y0 + q * 4);
    }
    const float* xpb = g_xp + (size_t)b * NF * TXX;
    for (int i = tid; i < 2560; i += 256) {
        int f = i >> 5, q = i & 31;
        *(float4*)&Xs[f * 128 + q * 4] =
            *(const float4*)(xpb + (size_t)f * TXX + t0 + q * 4);
    }
    __syncthreads();

    int tx = tid & 15;   // t
    int ty = tid >> 4;   // y

    float acc[8][8];
#pragma unroll
    for (int i = 0; i < 8; ++i)
#pragma unroll
        for (int j = 0; j < 8; ++j) acc[i][j] = 0.f;

#pragma unroll 4
    for (int f = 0; f < NF; ++f) {
        float4 ya = *(const float4*)&Ys[f * 128 + ty * 8];
        float4 yb4 = *(const float4*)&Ys[f * 128 + ty * 8 + 4];
        float4 xa = *(const float4*)&Xs[f * 128 + tx * 8];
        float4 xb4 = *(const float4*)&Xs[f * 128 + tx * 8 + 4];
        float yv[8] = {ya.x, ya.y, ya.z, ya.w, yb4.x, yb4.y, yb4.z, yb4.w};
        float xv[8] = {xa.x, xa.y, xa.z, xa.w, xb4.x, xb4.y, xb4.z, xb4.w};
#pragma unroll
        for (int i = 0; i < 8; ++i)
#pragma unroll
            for (int j = 0; j < 8; ++j) acc[i][j] += yv[i] * xv[j];
    }

    int tbase = t0 + tx * 8;
    float xsqv[8];
#pragma unroll
    for (int j = 0; j < 8; ++j) xsqv[j] = g_xsq[b * TXX + tbase + j];

#pragma unroll
    for (int i = 0; i < 8; ++i) {
        int yg = y0 + ty * 8 + i;
        if (yg >= ylen) continue;
        float ysv = g_ysq[b * TYY + yg];
        float ov[8];
#pragma unroll
        for (int j = 0; j < 8; ++j) {
            float val = ((ysv + acc[i][j]) + xsqv[j]) + CONSTF;
            ov[j] = (tbase + j < xlen) ? val : NEGF;
        }
        float* vout = g_v + ((size_t)b * TYY + yg) * TXX + tbase;
        *(float4*)(vout + 0) = make_float4(ov[0], ov[1], ov[2], ov[3]);
        *(float4*)(vout + 4) = make_float4(ov[4], ov[5], ov[6], ov[7]);
    }
}

// ---------------------------------------------------------------------------
// DP forward + backtrack.  One warp per batch.  Lane L owns t = 12L + j.
// Rows streamed through a 16-slot smem ring via cp.async, prefetch depth 14.
// Each lane copies exactly the 48B it later reads -> per-thread wait suffices.
__global__ __launch_bounds__(32) void dp_kernel(const int* __restrict__ xl,
                                                const int* __restrict__ yl) {
    extern __shared__ float smf[];
    float* ring = smf;                                       // [DSLOT][TXX]
    unsigned short* sdec = (unsigned short*)(smf + DSLOT * TXX);  // [TYY][32]

    int b = blockIdx.x;
    int lane = threadIdx.x;
    int ylen = yl[b], xlen = xl[b];

    const float* vb = g_v + (size_t)b * TYY * TXX;
    uint32_t ring_base = (uint32_t)__cvta_generic_to_shared(ring);
    uint32_t lane_off = (uint32_t)(lane * 12 * 4);  // bytes within a row

    // Prologue: prefetch rows 0..PF-1 (one commit group per row)
#pragma unroll
    for (int r = 0; r < PF; ++r) {
        uint32_t s = ring_base + (uint32_t)(r * TXX * 4) + lane_off;
        const float* g = vb + (size_t)r * TXX + lane * 12;
        cp16(s, g); cp16(s + 16, g + 4); cp16(s + 32, g + 8);
        asm volatile("cp.async.commit_group;\n" ::: "memory");
    }

    float q[12];
#pragma unroll
    for (int j = 0; j < 12; ++j) q[j] = NEGF;
    if (lane == 0) q[0] = 0.0f;

    for (int yy = 0; yy < ylen; ++yy) {
        // issue prefetch of row yy+PF into slot (yy+PF)%DSLOT
        {
            int pr = yy + PF; if (pr > TYY - 1) pr = TYY - 1;
            uint32_t slot = (uint32_t)((yy + PF) & (DSLOT - 1));
            uint32_t s = ring_base + slot * (uint32_t)(TXX * 4) + lane_off;
            const float* g = vb + (size_t)pr * TXX + lane * 12;
            cp16(s, g); cp16(s + 16, g + 4); cp16(s + 32, g + 8);
            asm volatile("cp.async.commit_group;\n" ::: "memory");
        }
        // wait until row yy's group has landed (<= PF groups outstanding)
        asm volatile("cp.async.wait_group %0;\n" :: "n"(PF) : "memory");

        const float4* rp = (const float4*)(ring + (yy & (DSLOT - 1)) * TXX + lane * 12);
        float4 c0 = rp[0], c1 = rp[1], c2 = rp[2];

        float carry = __shfl_up_sync(0xffffffffu, q[11], 1);
        if (lane == 0) carry = NEGF;
        float vv[12] = {c0.x, c0.y, c0.z, c0.w,
                        c1.x, c1.y, c1.z, c1.w,
                        c2.x, c2.y, c2.z, c2.w};
        unsigned bits = 0u;
#pragma unroll
        for (int j = 11; j >= 1; --j) {
            unsigned lt = (q[j] < q[j - 1]) ? 1u : 0u;
            bits |= lt << j;
            q[j] = vv[j] + fmaxf(q[j], q[j - 1]);
        }
        {
            unsigned lt = (q[0] < carry) ? 1u : 0u;
            bits |= lt;
            q[0] = vv[0] + fmaxf(q[0], carry);
        }
        sdec[yy * 32 + lane] = (unsigned short)bits;
    }
    asm volatile("cp.async.wait_all;\n" ::: "memory");
    __syncwarp();

#pragma unroll
    for (int j = 0; j < 12; ++j) g_dur[b * TXX + lane * 12 + j] = 0.0f;
    __syncwarp();

    if (lane == 0) {
        int idx = xlen - 1;
        int w = idx / 12, r = idx - w * 12;
        int cnt = 0;
        int* gi = g_idx + b * TYY;
        for (int yy = ylen - 1; yy >= 0; --yy) {
            gi[yy] = idx;
            cnt++;
            bool move = false;
            if (idx != 0 && yy > 0) {
                if (idx == yy) move = true;
                else move = ((sdec[yy * 32 + w] >> r) & 1u) != 0u;
            }
            if (move) {
                g_dur[b * TXX + idx] = (float)cnt;
                cnt = 0;
                idx--;
                if (--r < 0) { r = 11; w--; }
            }
        }
        g_dur[b * TXX + idx] = (float)cnt;
    }
}

// ---------------------------------------------------------------------------
// attn[b][t][s] = (s < ylen && g_idx[b][s] == t) ? 1 : 0
__global__ __launch_bounds__(128) void attn_kernel(const int* __restrict__ yl,
                                                   float* __restrict__ out) {
    int b = blockIdx.y;
    int t = blockIdx.x;
    int tid = threadIdx.x;
    int ylen = yl[b];
    const int* gi = g_idx + b * TYY;
    float* o = out + ((size_t)b * TXX + t) * TYY;
#pragma unroll
    for (int it = 0; it < 3; ++it) {
        int s4 = tid + it * 128;
        int s = s4 * 4;
        int4 iv = *(const int4*)(gi + s);
        float4 ov;
        ov.x = (s + 0 < ylen && iv.x == t) ? 1.f : 0.f;
        ov.y = (s + 1 < ylen && iv.y == t) ? 1.f : 0.f;
        ov.z = (s + 2 < ylen && iv.z == t) ? 1.f : 0.f;
        ov.w = (s + 3 < ylen && iv.w == t) ? 1.f : 0.f;
        *(float4*)(o + s) = ov;
    }
}

// ---------------------------------------------------------------------------
// loss + durations tail
__global__ __launch_bounds__(256) void loss_kernel(const float* __restrict__ pred,
                                                   const int* __restrict__ xl,
                                                   float* __restrict__ out,
                                                   int write_tail) {
    __shared__ float red[256];
    int tid = threadIdx.x;
    float s = 0.f;
    for (int i = tid; i < BB * TXX; i += 256) {
        int b = i / TXX, t = i - b * TXX;
        float dur = g_dur[i];
        float tl = (t < xl[b]) ? logf(dur + 1e-8f) : 0.0f;
        float d = pred[i] - tl;
        s += d * d;
        if (write_tail) out[ATTN_SZ + 1 + i] = dur;
    }
    red[tid] = s;
    __syncthreads();
    for (int off = 128; off > 0; off >>= 1) {
        if (tid < off) red[tid] += red[tid + off];
        __syncthreads();
    }
    if (tid == 0 && write_tail) {
        int sx = 0;
        for (int bb2 = 0; bb2 < BB; ++bb2) sx += xl[bb2];
        out[ATTN_SZ] = red[0] / (float)sx;
    }
}

// ---------------------------------------------------------------------------
extern "C" void kernel_launch(void* const* d_in, const int* in_sizes, int n_in,
                              void* d_out, int out_size) {
    const float* x    = (const float*)d_in[0];
    const float* y    = (const float*)d_in[1];
    const int*   xlen = (const int*)d_in[4];
    const int*   ylen = (const int*)d_in[5];
    const float* pred = (const float*)d_in[6];
    const float* W    = (const float*)d_in[7];
    const float* bias = (const float*)d_in[8];
    float* out = (float*)d_out;

    int dp_smem = DSLOT * TXX * (int)sizeof(float) + TYY * 32 * (int)sizeof(unsigned short);

    cudaFuncSetAttribute(cross_kernel, cudaFuncAttributeMaxDynamicSharedMemorySize,
                         2 * 80 * 128 * (int)sizeof(float));
    cudaFuncSetAttribute(dp_kernel, cudaFuncAttributeMaxDynamicSharedMemorySize,
                         dp_smem);

    ysq_kernel<<<dim3(TYY / 256, BB), 256>>>(y);
    xp_kernel<<<dim3(TXX / 128, BB), 160>>>(x, W, bias);
    cross_kernel<<<dim3(TXX / 128, TYY / 128, BB), 256,
                   2 * 80 * 128 * sizeof(float)>>>(y, xlen, ylen);
    dp_kernel<<<BB, 32, dp_smem>>>(xlen, ylen);
    attn_kernel<<<dim3(TXX, BB), 128>>>(ylen, out);

    int write_tail = ((size_t)out_size >= ATTN_SZ + 1 + BB * TXX) ? 1 : 0;
    loss_kernel<<<1, 256>>>(pred, xlen, out, write_tail);
}